// round 1
// baseline (speedup 1.0000x reference)
#include <cuda_runtime.h>

// ---------------------------------------------------------------------------
// Fused ScalarDotProductPolicyNetwork
//   per batch b (8192): two attention blocks over N=32 agents, D=128,
//   then MLP 128->256 (leaky_relu 0.01) -> 10 (softmax).
// Outputs concatenated: policy (B*32*10) | weight_1 (B*32*32) | weight (B*32*32)
// ---------------------------------------------------------------------------

#define BATCH 8192
#define NAG   32
#define DIM   128
#define HIDN  256
#define NACT  10

#define LDA 132   // padded row stride for 32x128 fp32 buffers
#define LDP 36    // padded row stride for 32x32 prob buffer
#define LDH 260   // padded row stride for 32x256 hidden buffer

#define INV_SCALE 0.08838834764831845f   // 1/sqrt(128)

#define POL_OFF 0
#define W1_OFF  2621440ul                 // B*32*10
#define W2_OFF  11010048ul                // + B*32*32

typedef unsigned long long u64;

// transposed weights, written by prep kernel each call (deterministic)
__device__ float g_Wt[6 * 128 * 128];     // Wk1t,Wq1t,Wv1t,Wk2t,Wq2t,Wv2t  [d][e]
__device__ float g_Wp1t[128 * 256];       // Wp1t [f][h]

// ---------------------------------------------------------------------------
// packed fp32x2 helpers
// ---------------------------------------------------------------------------
__device__ __forceinline__ u64 pk2(float x) {
    u64 r;
    asm("mov.b64 %0, {%1, %2};" : "=l"(r) : "f"(x), "f"(x));
    return r;
}
__device__ __forceinline__ void fma2(u64& d, u64 a, u64 b) {
    asm("fma.rn.f32x2 %0, %1, %2, %0;" : "+l"(d) : "l"(a), "l"(b));
}
__device__ __forceinline__ float2 up2(u64 v) {
    float2 f;
    asm("mov.b64 {%0, %1}, %2;" : "=f"(f.x), "=f"(f.y) : "l"(v));
    return f;
}

// ---------------------------------------------------------------------------
// prep: transpose all weight matrices once per launch
// ---------------------------------------------------------------------------
__global__ void prep_kernel(const float* __restrict__ Wk1, const float* __restrict__ Wq1,
                            const float* __restrict__ Wv1, const float* __restrict__ Wk2,
                            const float* __restrict__ Wq2, const float* __restrict__ Wv2,
                            const float* __restrict__ Wp1)
{
    int i = blockIdx.x * blockDim.x + threadIdx.x;
    if (i < 6 * 16384) {
        int m = i >> 14;
        int r = i & 16383;
        int e = r >> 7;       // out-feature row of W
        int d = r & 127;      // in-feature col of W
        const float* W;
        switch (m) {
            case 0: W = Wk1; break;
            case 1: W = Wq1; break;
            case 2: W = Wv1; break;
            case 3: W = Wk2; break;
            case 4: W = Wq2; break;
            default: W = Wv2; break;
        }
        g_Wt[m * 16384 + d * 128 + e] = W[e * 128 + d];
    } else {
        int r = i - 6 * 16384;
        if (r < 256 * 128) {
            int h = r >> 7;   // 0..255
            int f = r & 127;  // 0..127
            g_Wp1t[f * 256 + h] = Wp1[h * 128 + f];
        }
    }
}

// ---------------------------------------------------------------------------
// GEMM: C[32][128] = A[32][K] * Wt[K][128]   (Wt already transposed: [k][e])
// 256 threads, 4x4 tile per thread, packed fp32x2 FMA on column pairs.
// ---------------------------------------------------------------------------
__device__ __forceinline__ void gemm32(const float* __restrict__ A, int lda,
                                       const float* __restrict__ W, int ldw,
                                       float* __restrict__ C, int ldc,
                                       int K, bool relu)
{
    int tid = threadIdx.x;
    int n0 = (tid >> 5) * 4;   // row group: all lanes in a warp share n0 (broadcast A reads)
    int e0 = (tid & 31) * 4;   // col group: contiguous across lanes (conflict-free W reads)

    u64 acc[4][2] = {{0ull, 0ull}, {0ull, 0ull}, {0ull, 0ull}, {0ull, 0ull}};
    const float* a = A + n0 * lda;
    const float* wp = W + e0;

#pragma unroll 2
    for (int d = 0; d < K; d += 4) {
        const float* wr = wp + d * ldw;
        u64 w00 = *(const u64*)(wr);
        u64 w01 = *(const u64*)(wr + 2);
        u64 w10 = *(const u64*)(wr + ldw);
        u64 w11 = *(const u64*)(wr + ldw + 2);
        u64 w20 = *(const u64*)(wr + 2 * ldw);
        u64 w21 = *(const u64*)(wr + 2 * ldw + 2);
        u64 w30 = *(const u64*)(wr + 3 * ldw);
        u64 w31 = *(const u64*)(wr + 3 * ldw + 2);

        float4 s0 = *(const float4*)(a + d);
        float4 s1 = *(const float4*)(a + lda + d);
        float4 s2 = *(const float4*)(a + 2 * lda + d);
        float4 s3 = *(const float4*)(a + 3 * lda + d);

        // reorder so each accumulator is touched once per 8 FFMA2 (hide lat=4)
#define GSTEP(wj0, wj1, c0, c1, c2, c3)                              \
        {                                                            \
            u64 p0 = pk2(c0), p1 = pk2(c1), p2 = pk2(c2), p3 = pk2(c3); \
            fma2(acc[0][0], p0, wj0); fma2(acc[1][0], p1, wj0);      \
            fma2(acc[2][0], p2, wj0); fma2(acc[3][0], p3, wj0);      \
            fma2(acc[0][1], p0, wj1); fma2(acc[1][1], p1, wj1);      \
            fma2(acc[2][1], p2, wj1); fma2(acc[3][1], p3, wj1);      \
        }
        GSTEP(w00, w01, s0.x, s1.x, s2.x, s3.x)
        GSTEP(w10, w11, s0.y, s1.y, s2.y, s3.y)
        GSTEP(w20, w21, s0.z, s1.z, s2.z, s3.z)
        GSTEP(w30, w31, s0.w, s1.w, s2.w, s3.w)
#undef GSTEP
    }

#pragma unroll
    for (int i = 0; i < 4; i++) {
        float2 r0 = up2(acc[i][0]);
        float2 r1 = up2(acc[i][1]);
        float4 v = make_float4(r0.x, r0.y, r1.x, r1.y);
        if (relu) {
            v.x = v.x > 0.f ? v.x : 0.01f * v.x;
            v.y = v.y > 0.f ? v.y : 0.01f * v.y;
            v.z = v.z > 0.f ? v.z : 0.01f * v.z;
            v.w = v.w > 0.f ? v.w : 0.01f * v.w;
        }
        *(float4*)(C + (n0 + i) * ldc + e0) = v;
    }
}

// ---------------------------------------------------------------------------
// scores: P[32][32] = Q[32][128] . K[32][128]^T  (raw, unscaled)
// 2x2 tile per thread
// ---------------------------------------------------------------------------
__device__ __forceinline__ void scores32(const float* __restrict__ Q,
                                         const float* __restrict__ K,
                                         float* __restrict__ P)
{
    int tid = threadIdx.x;
    int n0 = (tid >> 4) * 2;
    int m0 = (tid & 15) * 2;
    float a00 = 0.f, a01 = 0.f, a10 = 0.f, a11 = 0.f;
#pragma unroll 4
    for (int d = 0; d < 128; d += 4) {
        float4 q0 = *(const float4*)(Q + n0 * LDA + d);
        float4 q1 = *(const float4*)(Q + (n0 + 1) * LDA + d);
        float4 k0 = *(const float4*)(K + m0 * LDA + d);
        float4 k1 = *(const float4*)(K + (m0 + 1) * LDA + d);
        a00 += q0.x * k0.x + q0.y * k0.y + q0.z * k0.z + q0.w * k0.w;
        a01 += q0.x * k1.x + q0.y * k1.y + q0.z * k1.z + q0.w * k1.w;
        a10 += q1.x * k0.x + q1.y * k0.y + q1.z * k0.z + q1.w * k0.w;
        a11 += q1.x * k1.x + q1.y * k1.y + q1.z * k1.z + q1.w * k1.w;
    }
    P[n0 * LDP + m0]           = a00;
    P[n0 * LDP + m0 + 1]       = a01;
    P[(n0 + 1) * LDP + m0]     = a10;
    P[(n0 + 1) * LDP + m0 + 1] = a11;
}

// ---------------------------------------------------------------------------
// row softmax over 32 (applies INV_SCALE), writes probs to smem + global
// ---------------------------------------------------------------------------
__device__ __forceinline__ void softmax_rows(float* P, float* __restrict__ gout)
{
    int w = threadIdx.x >> 5;
    int lane = threadIdx.x & 31;
#pragma unroll
    for (int r = 0; r < 4; r++) {
        int n = w * 4 + r;
        float x = P[n * LDP + lane] * INV_SCALE;
        float mx = x;
#pragma unroll
        for (int off = 16; off; off >>= 1)
            mx = fmaxf(mx, __shfl_xor_sync(0xffffffffu, mx, off));
        float e = expf(x - mx);
        float s = e;
#pragma unroll
        for (int off = 16; off; off >>= 1)
            s += __shfl_xor_sync(0xffffffffu, s, off);
        float p = e / s;
        P[n * LDP + lane] = p;
        gout[n * 32 + lane] = p;
    }
}

// ---------------------------------------------------------------------------
// smem staging helpers
// ---------------------------------------------------------------------------
__device__ __forceinline__ void stage_w128(const float* __restrict__ src, float* dst)
{
    int tid = threadIdx.x;
#pragma unroll
    for (int i = 0; i < 16; i++) {
        int idx4 = tid + i * 256;
        *(float4*)(dst + idx4 * 4) = *(const float4*)(src + idx4 * 4);
    }
}
// copy one 128-wide column half of Wp1t [f][h=256] into sW[128][128]
__device__ __forceinline__ void stage_wp1(const float* __restrict__ src, float* dst)
{
    int tid = threadIdx.x;
#pragma unroll
    for (int i = 0; i < 16; i++) {
        int idx4 = tid + i * 256;
        int f = idx4 >> 5;
        int c = idx4 & 31;
        *(float4*)(dst + f * 128 + c * 4) = *(const float4*)(src + f * 256 + c * 4);
    }
}

// ---------------------------------------------------------------------------
// fused main kernel: one CTA per batch, 256 threads
// ---------------------------------------------------------------------------
__global__ void __launch_bounds__(256, 1)
fused_kernel(const float* __restrict__ states, const float* __restrict__ Wp2,
             float* __restrict__ out)
{
    extern __shared__ float sm[];
    float* sIn  = sm;                  // 32*132 = 4224
    float* sK   = sIn + 4224;          // 4224
    float* sQ   = sK + 4224;           // 4224
    float* sV   = sQ + 4224;           // 4224
    float* sP   = sV + 4224;           // 32*36 = 1152
    float* sH   = sP + 1152;           // 32*260 = 8320
    float* sWp2 = sH + 8320;           // 2560
    float* sLog = sWp2 + 2560;         // 32*12 = 384
    float* sW   = sLog + 384;          // 16384
    // total 45696 floats = 182784 bytes

    int b = blockIdx.x;
    int tid = threadIdx.x;
    const float* st = states + (size_t)b * (NAG * DIM);

    // stage states, Wp2, and Wk1t together
#pragma unroll
    for (int i = 0; i < 4; i++) {
        int idx4 = tid + i * 256;              // 0..1023
        int n = idx4 >> 5;
        int c = idx4 & 31;
        *(float4*)(sIn + n * LDA + c * 4) = *(const float4*)(st + idx4 * 4);
    }
#pragma unroll
    for (int i = 0; i < 3; i++) {
        int idx4 = tid + i * 256;
        if (idx4 < 640)
            *(float4*)(sWp2 + idx4 * 4) = *(const float4*)(Wp2 + idx4 * 4);
    }
    stage_w128(g_Wt, sW);
    __syncthreads();

    // ---- attention block 1 ----
    gemm32(sIn, LDA, sW, 128, sK, LDA, 128, false);
    __syncthreads();
    stage_w128(g_Wt + 16384, sW);
    __syncthreads();
    gemm32(sIn, LDA, sW, 128, sQ, LDA, 128, false);
    __syncthreads();
    stage_w128(g_Wt + 2 * 16384, sW);
    __syncthreads();
    gemm32(sIn, LDA, sW, 128, sV, LDA, 128, false);
    __syncthreads();

    scores32(sQ, sK, sP);
    __syncthreads();
    softmax_rows(sP, out + W1_OFF + (size_t)b * 1024);
    __syncthreads();
    gemm32(sP, LDP, sV, LDA, sIn, LDA, 32, false);   // wav -> sIn
    __syncthreads();

    // ---- attention block 2 ----
    stage_w128(g_Wt + 3 * 16384, sW);
    __syncthreads();
    gemm32(sIn, LDA, sW, 128, sK, LDA, 128, false);
    __syncthreads();
    stage_w128(g_Wt + 4 * 16384, sW);
    __syncthreads();
    gemm32(sIn, LDA, sW, 128, sQ, LDA, 128, false);
    __syncthreads();
    stage_w128(g_Wt + 5 * 16384, sW);
    __syncthreads();
    gemm32(sIn, LDA, sW, 128, sV, LDA, 128, false);
    __syncthreads();

    scores32(sQ, sK, sP);
    __syncthreads();
    softmax_rows(sP, out + W2_OFF + (size_t)b * 1024);
    __syncthreads();
    gemm32(sP, LDP, sV, LDA, sIn, LDA, 32, false);   // node_features -> sIn
    __syncthreads();

    // ---- policy head ----
    stage_wp1(g_Wp1t, sW);
    __syncthreads();
    gemm32(sIn, LDA, sW, 128, sH, LDH, 128, true);          // h[:, 0:128]
    __syncthreads();
    stage_wp1(g_Wp1t + 128, sW);
    __syncthreads();
    gemm32(sIn, LDA, sW, 128, sH + 128, LDH, 128, true);    // h[:, 128:256]
    __syncthreads();

    // logits: 320 dots of length 256
#pragma unroll
    for (int rep = 0; rep < 2; rep++) {
        int o = tid + rep * 256;
        if (o < 320) {
            int n = o / 10;
            int aa = o % 10;
            const float* hrow = sH + n * LDH;
            const float* wrow = sWp2 + aa * 256;
            float acc = 0.f;
#pragma unroll 4
            for (int j = 0; j < 256; j += 4) {
                float4 h4 = *(const float4*)(hrow + j);
                float4 w4 = *(const float4*)(wrow + j);
                acc += h4.x * w4.x + h4.y * w4.y + h4.z * w4.z + h4.w * w4.w;
            }
            sLog[n * 12 + aa] = acc;
        }
    }
    __syncthreads();

    // softmax over 10 actions, one row per lane of warp 0
    if (tid < 32) {
        int n = tid;
        float l[10];
        float mx = -1e30f;
#pragma unroll
        for (int a2 = 0; a2 < 10; a2++) {
            l[a2] = sLog[n * 12 + a2];
            mx = fmaxf(mx, l[a2]);
        }
        float s = 0.f;
#pragma unroll
        for (int a2 = 0; a2 < 10; a2++) {
            l[a2] = expf(l[a2] - mx);
            s += l[a2];
        }
        float inv = 1.0f / s;
        float* po = out + POL_OFF + (size_t)b * 320 + n * 10;
#pragma unroll
        for (int a2 = 0; a2 < 10; a2++)
            po[a2] = l[a2] * inv;
    }
}

// ---------------------------------------------------------------------------
// launch
// ---------------------------------------------------------------------------
extern "C" void kernel_launch(void* const* d_in, const int* in_sizes, int n_in,
                              void* d_out, int out_size)
{
    const float* states = (const float*)d_in[0];
    const float* Wk1 = (const float*)d_in[1];
    const float* Wq1 = (const float*)d_in[2];
    const float* Wv1 = (const float*)d_in[3];
    const float* Wk2 = (const float*)d_in[4];
    const float* Wq2 = (const float*)d_in[5];
    const float* Wv2 = (const float*)d_in[6];
    const float* Wp1 = (const float*)d_in[7];
    const float* Wp2 = (const float*)d_in[8];
    float* out = (float*)d_out;

    const int smem_bytes = 45696 * 4;   // 182784
    cudaFuncSetAttribute(fused_kernel, cudaFuncAttributeMaxDynamicSharedMemorySize,
                         smem_bytes);

    prep_kernel<<<512, 256>>>(Wk1, Wq1, Wv1, Wk2, Wq2, Wv2, Wp1);
    fused_kernel<<<BATCH, 256, smem_bytes>>>(states, Wp2, out);
}

// round 2
// speedup vs baseline: 1.0012x; 1.0012x over previous
#include <cuda_runtime.h>

// ---------------------------------------------------------------------------
// Fused ScalarDotProductPolicyNetwork
//   per batch b (8192): two attention blocks over N=32 agents, D=128,
//   then MLP 128->256 (leaky_relu 0.01) -> 10 (softmax).
// Outputs concatenated: policy (B*32*10) | weight_1 (B*32*32) | weight (B*32*32)
// ---------------------------------------------------------------------------

#define BATCH 8192
#define NAG   32
#define DIM   128
#define HIDN  256
#define NACT  10

#define LDA 132   // padded row stride for 32x128 fp32 buffers
#define LDP 36    // padded row stride for 32x32 prob buffer
#define LDH 260   // padded row stride for 32x256 hidden buffer

#define INV_SCALE 0.08838834764831845f   // 1/sqrt(128)

#define POL_OFF 0
#define W1_OFF  2621440ul                 // B*32*10
#define W2_OFF  11010048ul                // + B*32*32

typedef unsigned long long u64;

// transposed weights, written by prep kernel each call (deterministic)
__device__ float g_Wt[6 * 128 * 128];     // Wk1t,Wq1t,Wv1t,Wk2t,Wq2t,Wv2t  [d][e]
__device__ float g_Wp1t[128 * 256];       // Wp1t [f][h]

// ---------------------------------------------------------------------------
// packed fp32x2 helpers
// ---------------------------------------------------------------------------
__device__ __forceinline__ u64 pk2(float x) {
    u64 r;
    asm("mov.b64 %0, {%1, %2};" : "=l"(r) : "f"(x), "f"(x));
    return r;
}
__device__ __forceinline__ void fma2(u64& d, u64 a, u64 b) {
    asm("fma.rn.f32x2 %0, %1, %2, %0;" : "+l"(d) : "l"(a), "l"(b));
}
__device__ __forceinline__ float2 up2(u64 v) {
    float2 f;
    asm("mov.b64 {%0, %1}, %2;" : "=f"(f.x), "=f"(f.y) : "l"(v));
    return f;
}

// ---------------------------------------------------------------------------
// prep: transpose all weight matrices once per launch
// ---------------------------------------------------------------------------
__global__ void prep_kernel(const float* __restrict__ Wk1, const float* __restrict__ Wq1,
                            const float* __restrict__ Wv1, const float* __restrict__ Wk2,
                            const float* __restrict__ Wq2, const float* __restrict__ Wv2,
                            const float* __restrict__ Wp1)
{
    int i = blockIdx.x * blockDim.x + threadIdx.x;
    if (i < 6 * 16384) {
        int m = i >> 14;
        int r = i & 16383;
        int e = r >> 7;       // out-feature row of W
        int d = r & 127;      // in-feature col of W
        const float* W;
        switch (m) {
            case 0: W = Wk1; break;
            case 1: W = Wq1; break;
            case 2: W = Wv1; break;
            case 3: W = Wk2; break;
            case 4: W = Wq2; break;
            default: W = Wv2; break;
        }
        g_Wt[m * 16384 + d * 128 + e] = W[e * 128 + d];
    } else {
        int r = i - 6 * 16384;
        if (r < 256 * 128) {
            int h = r >> 7;   // 0..255
            int f = r & 127;  // 0..127
            g_Wp1t[f * 256 + h] = Wp1[h * 128 + f];
        }
    }
}

// ---------------------------------------------------------------------------
// GEMM: C[32][128] = A[32][K] * Wt[K][128]   (Wt already transposed: [k][e])
// 256 threads, 4x4 tile per thread, packed fp32x2 FMA on column pairs.
// ---------------------------------------------------------------------------
__device__ __forceinline__ void gemm32(const float* __restrict__ A, int lda,
                                       const float* __restrict__ W, int ldw,
                                       float* __restrict__ C, int ldc,
                                       int K, bool relu)
{
    int tid = threadIdx.x;
    int n0 = (tid >> 5) * 4;   // row group: all lanes in a warp share n0 (broadcast A reads)
    int e0 = (tid & 31) * 4;   // col group: contiguous across lanes (conflict-free W reads)

    u64 acc[4][2] = {{0ull, 0ull}, {0ull, 0ull}, {0ull, 0ull}, {0ull, 0ull}};
    const float* a = A + n0 * lda;
    const float* wp = W + e0;

#pragma unroll 2
    for (int d = 0; d < K; d += 4) {
        const float* wr = wp + d * ldw;
        u64 w00 = *(const u64*)(wr);
        u64 w01 = *(const u64*)(wr + 2);
        u64 w10 = *(const u64*)(wr + ldw);
        u64 w11 = *(const u64*)(wr + ldw + 2);
        u64 w20 = *(const u64*)(wr + 2 * ldw);
        u64 w21 = *(const u64*)(wr + 2 * ldw + 2);
        u64 w30 = *(const u64*)(wr + 3 * ldw);
        u64 w31 = *(const u64*)(wr + 3 * ldw + 2);

        float4 s0 = *(const float4*)(a + d);
        float4 s1 = *(const float4*)(a + lda + d);
        float4 s2 = *(const float4*)(a + 2 * lda + d);
        float4 s3 = *(const float4*)(a + 3 * lda + d);

        // reorder so each accumulator is touched once per 8 FFMA2 (hide lat=4)
#define GSTEP(wj0, wj1, c0, c1, c2, c3)                              \
        {                                                            \
            u64 p0 = pk2(c0), p1 = pk2(c1), p2 = pk2(c2), p3 = pk2(c3); \
            fma2(acc[0][0], p0, wj0); fma2(acc[1][0], p1, wj0);      \
            fma2(acc[2][0], p2, wj0); fma2(acc[3][0], p3, wj0);      \
            fma2(acc[0][1], p0, wj1); fma2(acc[1][1], p1, wj1);      \
            fma2(acc[2][1], p2, wj1); fma2(acc[3][1], p3, wj1);      \
        }
        GSTEP(w00, w01, s0.x, s1.x, s2.x, s3.x)
        GSTEP(w10, w11, s0.y, s1.y, s2.y, s3.y)
        GSTEP(w20, w21, s0.z, s1.z, s2.z, s3.z)
        GSTEP(w30, w31, s0.w, s1.w, s2.w, s3.w)
#undef GSTEP
    }

#pragma unroll
    for (int i = 0; i < 4; i++) {
        float2 r0 = up2(acc[i][0]);
        float2 r1 = up2(acc[i][1]);
        float4 v = make_float4(r0.x, r0.y, r1.x, r1.y);
        if (relu) {
            v.x = v.x > 0.f ? v.x : 0.01f * v.x;
            v.y = v.y > 0.f ? v.y : 0.01f * v.y;
            v.z = v.z > 0.f ? v.z : 0.01f * v.z;
            v.w = v.w > 0.f ? v.w : 0.01f * v.w;
        }
        *(float4*)(C + (n0 + i) * ldc + e0) = v;
    }
}

// ---------------------------------------------------------------------------
// scores: P[32][32] = Q[32][128] . K[32][128]^T  (raw, unscaled)
// 2x2 tile per thread
// ---------------------------------------------------------------------------
__device__ __forceinline__ void scores32(const float* __restrict__ Q,
                                         const float* __restrict__ K,
                                         float* __restrict__ P)
{
    int tid = threadIdx.x;
    int n0 = (tid >> 4) * 2;
    int m0 = (tid & 15) * 2;
    float a00 = 0.f, a01 = 0.f, a10 = 0.f, a11 = 0.f;
#pragma unroll 4
    for (int d = 0; d < 128; d += 4) {
        float4 q0 = *(const float4*)(Q + n0 * LDA + d);
        float4 q1 = *(const float4*)(Q + (n0 + 1) * LDA + d);
        float4 k0 = *(const float4*)(K + m0 * LDA + d);
        float4 k1 = *(const float4*)(K + (m0 + 1) * LDA + d);
        a00 += q0.x * k0.x + q0.y * k0.y + q0.z * k0.z + q0.w * k0.w;
        a01 += q0.x * k1.x + q0.y * k1.y + q0.z * k1.z + q0.w * k1.w;
        a10 += q1.x * k0.x + q1.y * k0.y + q1.z * k0.z + q1.w * k0.w;
        a11 += q1.x * k1.x + q1.y * k1.y + q1.z * k1.z + q1.w * k1.w;
    }
    P[n0 * LDP + m0]           = a00;
    P[n0 * LDP + m0 + 1]       = a01;
    P[(n0 + 1) * LDP + m0]     = a10;
    P[(n0 + 1) * LDP + m0 + 1] = a11;
}

// ---------------------------------------------------------------------------
// row softmax over 32 (applies INV_SCALE), writes probs to smem + global
// ---------------------------------------------------------------------------
__device__ __forceinline__ void softmax_rows(float* P, float* __restrict__ gout)
{
    int w = threadIdx.x >> 5;
    int lane = threadIdx.x & 31;
#pragma unroll
    for (int r = 0; r < 4; r++) {
        int n = w * 4 + r;
        float x = P[n * LDP + lane] * INV_SCALE;
        float mx = x;
#pragma unroll
        for (int off = 16; off; off >>= 1)
            mx = fmaxf(mx, __shfl_xor_sync(0xffffffffu, mx, off));
        float e = expf(x - mx);
        float s = e;
#pragma unroll
        for (int off = 16; off; off >>= 1)
            s += __shfl_xor_sync(0xffffffffu, s, off);
        float p = e / s;
        P[n * LDP + lane] = p;
        gout[n * 32 + lane] = p;
    }
}

// ---------------------------------------------------------------------------
// smem staging helpers
// ---------------------------------------------------------------------------
__device__ __forceinline__ void stage_w128(const float* __restrict__ src, float* dst)
{
    int tid = threadIdx.x;
#pragma unroll
    for (int i = 0; i < 16; i++) {
        int idx4 = tid + i * 256;
        *(float4*)(dst + idx4 * 4) = *(const float4*)(src + idx4 * 4);
    }
}
// copy one 128-wide column half of Wp1t [f][h=256] into sW[128][128]
__device__ __forceinline__ void stage_wp1(const float* __restrict__ src, float* dst)
{
    int tid = threadIdx.x;
#pragma unroll
    for (int i = 0; i < 16; i++) {
        int idx4 = tid + i * 256;
        int f = idx4 >> 5;
        int c = idx4 & 31;
        *(float4*)(dst + f * 128 + c * 4) = *(const float4*)(src + f * 256 + c * 4);
    }
}

// ---------------------------------------------------------------------------
// fused main kernel: one CTA per batch, 256 threads
// ---------------------------------------------------------------------------
__global__ void __launch_bounds__(256, 1)
fused_kernel(const float* __restrict__ states, const float* __restrict__ Wp2,
             float* __restrict__ out)
{
    extern __shared__ float sm[];
    float* sIn  = sm;                  // 32*132 = 4224
    float* sK   = sIn + 4224;          // 4224
    float* sQ   = sK + 4224;           // 4224
    float* sV   = sQ + 4224;           // 4224
    float* sP   = sV + 4224;           // 32*36 = 1152
    float* sH   = sP + 1152;           // 32*260 = 8320
    float* sWp2 = sH + 8320;           // 2560
    float* sLog = sWp2 + 2560;         // 32*12 = 384
    float* sW   = sLog + 384;          // 16384
    // total 45696 floats = 182784 bytes

    int b = blockIdx.x;
    int tid = threadIdx.x;
    const float* st = states + (size_t)b * (NAG * DIM);

    // stage states, Wp2, and Wk1t together
#pragma unroll
    for (int i = 0; i < 4; i++) {
        int idx4 = tid + i * 256;              // 0..1023
        int n = idx4 >> 5;
        int c = idx4 & 31;
        *(float4*)(sIn + n * LDA + c * 4) = *(const float4*)(st + idx4 * 4);
    }
#pragma unroll
    for (int i = 0; i < 3; i++) {
        int idx4 = tid + i * 256;
        if (idx4 < 640)
            *(float4*)(sWp2 + idx4 * 4) = *(const float4*)(Wp2 + idx4 * 4);
    }
    stage_w128(g_Wt, sW);
    __syncthreads();

    // ---- attention block 1 ----
    gemm32(sIn, LDA, sW, 128, sK, LDA, 128, false);
    __syncthreads();
    stage_w128(g_Wt + 16384, sW);
    __syncthreads();
    gemm32(sIn, LDA, sW, 128, sQ, LDA, 128, false);
    __syncthreads();
    stage_w128(g_Wt + 2 * 16384, sW);
    __syncthreads();
    gemm32(sIn, LDA, sW, 128, sV, LDA, 128, false);
    __syncthreads();

    scores32(sQ, sK, sP);
    __syncthreads();
    softmax_rows(sP, out + W1_OFF + (size_t)b * 1024);
    __syncthreads();
    gemm32(sP, LDP, sV, LDA, sIn, LDA, 32, false);   // wav -> sIn
    __syncthreads();

    // ---- attention block 2 ----
    stage_w128(g_Wt + 3 * 16384, sW);
    __syncthreads();
    gemm32(sIn, LDA, sW, 128, sK, LDA, 128, false);
    __syncthreads();
    stage_w128(g_Wt + 4 * 16384, sW);
    __syncthreads();
    gemm32(sIn, LDA, sW, 128, sQ, LDA, 128, false);
    __syncthreads();
    stage_w128(g_Wt + 5 * 16384, sW);
    __syncthreads();
    gemm32(sIn, LDA, sW, 128, sV, LDA, 128, false);
    __syncthreads();

    scores32(sQ, sK, sP);
    __syncthreads();
    softmax_rows(sP, out + W2_OFF + (size_t)b * 1024);
    __syncthreads();
    gemm32(sP, LDP, sV, LDA, sIn, LDA, 32, false);   // node_features -> sIn
    __syncthreads();

    // ---- policy head ----
    stage_wp1(g_Wp1t, sW);
    __syncthreads();
    gemm32(sIn, LDA, sW, 128, sH, LDH, 128, true);          // h[:, 0:128]
    __syncthreads();
    stage_wp1(g_Wp1t + 128, sW);
    __syncthreads();
    gemm32(sIn, LDA, sW, 128, sH + 128, LDH, 128, true);    // h[:, 128:256]
    __syncthreads();

    // logits: 320 dots of length 256
#pragma unroll
    for (int rep = 0; rep < 2; rep++) {
        int o = tid + rep * 256;
        if (o < 320) {
            int n = o / 10;
            int aa = o % 10;
            const float* hrow = sH + n * LDH;
            const float* wrow = sWp2 + aa * 256;
            float acc = 0.f;
#pragma unroll 4
            for (int j = 0; j < 256; j += 4) {
                float4 h4 = *(const float4*)(hrow + j);
                float4 w4 = *(const float4*)(wrow + j);
                acc += h4.x * w4.x + h4.y * w4.y + h4.z * w4.z + h4.w * w4.w;
            }
            sLog[n * 12 + aa] = acc;
        }
    }
    __syncthreads();

    // softmax over 10 actions, one row per lane of warp 0
    if (tid < 32) {
        int n = tid;
        float l[10];
        float mx = -1e30f;
#pragma unroll
        for (int a2 = 0; a2 < 10; a2++) {
            l[a2] = sLog[n * 12 + a2];
            mx = fmaxf(mx, l[a2]);
        }
        float s = 0.f;
#pragma unroll
        for (int a2 = 0; a2 < 10; a2++) {
            l[a2] = expf(l[a2] - mx);
            s += l[a2];
        }
        float inv = 1.0f / s;
        float* po = out + POL_OFF + (size_t)b * 320 + n * 10;
#pragma unroll
        for (int a2 = 0; a2 < 10; a2++)
            po[a2] = l[a2] * inv;
    }
}

// ---------------------------------------------------------------------------
// launch
// ---------------------------------------------------------------------------
extern "C" void kernel_launch(void* const* d_in, const int* in_sizes, int n_in,
                              void* d_out, int out_size)
{
    const float* states = (const float*)d_in[0];
    const float* Wk1 = (const float*)d_in[1];
    const float* Wq1 = (const float*)d_in[2];
    const float* Wv1 = (const float*)d_in[3];
    const float* Wk2 = (const float*)d_in[4];
    const float* Wq2 = (const float*)d_in[5];
    const float* Wv2 = (const float*)d_in[6];
    const float* Wp1 = (const float*)d_in[7];
    const float* Wp2 = (const float*)d_in[8];
    float* out = (float*)d_out;

    const int smem_bytes = 45696 * 4;   // 182784
    cudaFuncSetAttribute(fused_kernel, cudaFuncAttributeMaxDynamicSharedMemorySize,
                         smem_bytes);

    prep_kernel<<<512, 256>>>(Wk1, Wq1, Wv1, Wk2, Wq2, Wv2, Wp1);
    fused_kernel<<<BATCH, 256, smem_bytes>>>(states, Wp2, out);
}